// round 4
// baseline (speedup 1.0000x reference)
#include <cuda_runtime.h>
#include <math.h>

#define NODES 100000
#define FEAT  128

// Scratch: __device__ globals (allocation-free rule).
__device__ float g_g[NODES * FEAT];    // g = (in @ W) * dinv
__device__ float g_agg[NODES * FEAT];  // aggregation buffer (init = g, self loop)
__device__ float g_h[NODES * FEAT];    // layer output / next layer input
__device__ float g_dinv[NODES];        // deg -> dinv in place
__device__ int   g_idx64;              // 1 if edge_index is int64, 0 if int32

// ---------------------------------------------------------------------------
// Edge-index dtype detection (device-side, deterministic, capture-safe).
// Interpret first 256 entries as int64: if all in [0, NODES) -> int64 layout,
// else the buffer is int32.
// ---------------------------------------------------------------------------
__global__ void k_detect(const void* __restrict__ ei) {
    __shared__ int ok;
    if (threadIdx.x == 0) ok = 1;
    __syncthreads();
    long long v = ((const long long*)ei)[threadIdx.x];
    if (v < 0 || v >= NODES) ok = 0;   // benign race: only writes 0
    __syncthreads();
    if (threadIdx.x == 0) g_idx64 = ok;
}

__device__ __forceinline__ int load_idx(const void* ei, long long elem) {
    if (g_idx64) return (int)((const long long*)ei)[elem];
    return ((const int*)ei)[elem];
}

// ---------------------------------------------------------------------------
// degree kernels
// ---------------------------------------------------------------------------
__global__ void k_fill_deg(int n) {
    int i = blockIdx.x * blockDim.x + threadIdx.x;
    if (i < n) g_dinv[i] = 1.0f;  // self loop
}

__global__ void k_count_deg(const void* __restrict__ ei, int E) {
    int e = blockIdx.x * blockDim.x + threadIdx.x;
    if (e >= E) return;
    int d = load_idx(ei, (long long)E + e);   // dst = second row
    if (d >= 0 && d < NODES) atomicAdd(&g_dinv[d], 1.0f);
}

__global__ void k_rsqrt(int n) {
    int i = blockIdx.x * blockDim.x + threadIdx.x;
    if (i < n) g_dinv[i] = rsqrtf(g_dinv[i]);
}

// ---------------------------------------------------------------------------
// GEMM: g[row][c] = (sum_k A[row][k] * W[k][c]) * dinv[row]; agg gets a copy.
// BM=128, BN=128, BK=32 (4 chunks). 256 threads, 8x8 microtile per thread.
// Static shared: 128*33*4 + 32*128*4 = 33280 B.
// use_h != 0 selects the internal g_h buffer as input (layer 2).
// ---------------------------------------------------------------------------
__global__ void k_gemm_scale(const float* __restrict__ Aext,
                             const float* __restrict__ W,
                             int n, int use_h) {
    __shared__ float  xs[128 * 33];     // padded: row stride 33 floats
    __shared__ float4 ws4[32 * 32];     // [32 k-rows][128 cols] as float4

    const float* A = use_h ? (const float*)g_h : Aext;

    int tid = threadIdx.x;
    int tx = tid & 15;        // 16 col-groups of 8
    int ty = tid >> 4;        // 16 row-groups of 8
    int row0 = blockIdx.x * 128;

    const float4* A4 = (const float4*)A;
    const float4* W4 = (const float4*)W;

    float acc[8][8];
#pragma unroll
    for (int r = 0; r < 8; r++)
#pragma unroll
        for (int c = 0; c < 8; c++) acc[r][c] = 0.f;

    for (int kc = 0; kc < 4; kc++) {
#pragma unroll
        for (int i = 0; i < 4; i++) {
            int slot = tid + i * 256;          // 0..1023
            int r  = slot >> 3;                // tile row 0..127
            int c4 = slot & 7;                 // float4 within 32-k chunk
            int gr = row0 + r;
            float4 v = (gr < n) ? A4[gr * 32 + kc * 8 + c4]
                                : make_float4(0.f, 0.f, 0.f, 0.f);
            float* p = &xs[r * 33 + c4 * 4];
            p[0] = v.x; p[1] = v.y; p[2] = v.z; p[3] = v.w;
        }
#pragma unroll
        for (int i = 0; i < 4; i++) {
            int slot = tid + i * 256;          // 0..1023
            int kr = slot >> 5;                // 0..31
            int c4 = slot & 31;                // 0..31
            ws4[slot] = W4[(kc * 32 + kr) * 32 + c4];
        }
        __syncthreads();

#pragma unroll 8
        for (int k = 0; k < 32; k++) {
            float a[8];
#pragma unroll
            for (int r = 0; r < 8; r++) a[r] = xs[(ty * 8 + r) * 33 + k];
            float4 b0 = ws4[k * 32 + tx * 2];
            float4 b1 = ws4[k * 32 + tx * 2 + 1];
#pragma unroll
            for (int r = 0; r < 8; r++) {
                acc[r][0] += a[r] * b0.x;
                acc[r][1] += a[r] * b0.y;
                acc[r][2] += a[r] * b0.z;
                acc[r][3] += a[r] * b0.w;
                acc[r][4] += a[r] * b1.x;
                acc[r][5] += a[r] * b1.y;
                acc[r][6] += a[r] * b1.z;
                acc[r][7] += a[r] * b1.w;
            }
        }
        __syncthreads();
    }

    float4* gout = (float4*)g_g;
    float4* aout = (float4*)g_agg;
#pragma unroll
    for (int r = 0; r < 8; r++) {
        int row = row0 + ty * 8 + r;
        if (row < n) {
            float dv = g_dinv[row];
            float4 o0 = make_float4(acc[r][0] * dv, acc[r][1] * dv,
                                    acc[r][2] * dv, acc[r][3] * dv);
            float4 o1 = make_float4(acc[r][4] * dv, acc[r][5] * dv,
                                    acc[r][6] * dv, acc[r][7] * dv);
            int base = row * 32 + tx * 2;
            gout[base]     = o0;
            gout[base + 1] = o1;
            aout[base]     = o0;
            aout[base + 1] = o1;
        }
    }
}

// ---------------------------------------------------------------------------
// Edge scatter: agg[dst] += g[src]. One warp per edge, float4 per lane.
// ---------------------------------------------------------------------------
__global__ void k_scatter(const void* __restrict__ ei, int E) {
    int idx = blockIdx.x * blockDim.x + threadIdx.x;
    int e = idx >> 5;
    if (e >= E) return;
    int q = idx & 31;
    int s = load_idx(ei, e);                    // src = first row
    int d = load_idx(ei, (long long)E + e);     // dst = second row
    if ((unsigned)s >= NODES || (unsigned)d >= NODES) return;  // safety
    float4 v = ((const float4*)g_g)[s * 32 + q];
    float* a = g_agg + d * 128 + q * 4;
    atomicAdd(a,     v.x);
    atomicAdd(a + 1, v.y);
    atomicAdd(a + 2, v.z);
    atomicAdd(a + 3, v.w);
}

// ---------------------------------------------------------------------------
// finish: h = relu(dinv[i] * agg[i,:] + b)
// ---------------------------------------------------------------------------
__global__ void k_finish(const float* __restrict__ b, int n) {
    int idx = blockIdx.x * blockDim.x + threadIdx.x;
    if (idx >= n * 32) return;
    int i = idx >> 5;
    int q = idx & 31;
    float dv = g_dinv[i];
    float4 a = ((const float4*)g_agg)[i * 32 + q];
    float4 bb = ((const float4*)b)[q];
    float4 o;
    o.x = fmaxf(dv * a.x + bb.x, 0.f);
    o.y = fmaxf(dv * a.y + bb.y, 0.f);
    o.z = fmaxf(dv * a.z + bb.z, 0.f);
    o.w = fmaxf(dv * a.w + bb.w, 0.f);
    ((float4*)g_h)[i * 32 + q] = o;
}

// ---------------------------------------------------------------------------
// FC + log_softmax: warp per node.
// ---------------------------------------------------------------------------
__global__ void k_fc(const float* __restrict__ Wfc,   // [128][2]
                     const float* __restrict__ bfc,   // [2]
                     float* __restrict__ out,         // [n][2]
                     int n) {
    int idx = blockIdx.x * blockDim.x + threadIdx.x;
    int i = idx >> 5;
    int lane = idx & 31;
    if (i >= n) return;

    float4 hv = ((const float4*)g_h)[i * 32 + lane];  // feats 4l..4l+3
    const float4* w4 = (const float4*)Wfc;            // 2 rows x 2 cols per float4
    float4 w0 = w4[lane * 2];                         // rows 4l, 4l+1
    float4 w1 = w4[lane * 2 + 1];                     // rows 4l+2, 4l+3

    float l0 = hv.x * w0.x + hv.y * w0.z + hv.z * w1.x + hv.w * w1.z;
    float l1 = hv.x * w0.y + hv.y * w0.w + hv.z * w1.y + hv.w * w1.w;

#pragma unroll
    for (int o = 16; o > 0; o >>= 1) {
        l0 += __shfl_xor_sync(0xffffffffu, l0, o);
        l1 += __shfl_xor_sync(0xffffffffu, l1, o);
    }

    if (lane == 0) {
        l0 += bfc[0];
        l1 += bfc[1];
        float m = fmaxf(l0, l1);
        float z = m + logf(expf(l0 - m) + expf(l1 - m));
        out[i * 2]     = l0 - z;
        out[i * 2 + 1] = l1 - z;
    }
}

// ---------------------------------------------------------------------------
extern "C" void kernel_launch(void* const* d_in, const int* in_sizes, int n_in,
                              void* d_out, int out_size) {
    const float* x   = (const float*)d_in[0];
    const void*  ei  = d_in[1];                 // int32 or int64, detected on device
    const float* W1  = (const float*)d_in[2];
    const float* b1  = (const float*)d_in[3];
    const float* W2  = (const float*)d_in[4];
    const float* b2  = (const float*)d_in[5];
    const float* Wfc = (const float*)d_in[6];
    const float* bfc = (const float*)d_in[7];
    float*       out = (float*)d_out;

    int n = in_sizes[0] / FEAT;
    int E = in_sizes[1] / 2;

    int tb = 256;
    int gemm_blocks = (n + 127) / 128;
    long long scat_total = (long long)E * 32;
    int scat_blocks = (int)((scat_total + tb - 1) / tb);
    int elem_blocks = (n * 32 + tb - 1) / tb;

    // dtype detection + degrees
    k_detect<<<1, 256>>>(ei);
    k_fill_deg<<<(n + tb - 1) / tb, tb>>>(n);
    k_count_deg<<<(E + tb - 1) / tb, tb>>>(ei, E);
    k_rsqrt<<<(n + tb - 1) / tb, tb>>>(n);

    // layer 1
    k_gemm_scale<<<gemm_blocks, tb>>>(x, W1, n, 0);
    k_scatter<<<scat_blocks, tb>>>(ei, E);
    k_finish<<<elem_blocks, tb>>>(b1, n);

    // layer 2 (input = g_h, selected device-side)
    k_gemm_scale<<<gemm_blocks, tb>>>(x, W2, n, 1);
    k_scatter<<<scat_blocks, tb>>>(ei, E);
    k_finish<<<elem_blocks, tb>>>(b2, n);

    // FC + log_softmax
    k_fc<<<elem_blocks, tb>>>(Wfc, bfc, out, n);
}

// round 5
// speedup vs baseline: 3.4980x; 3.4980x over previous
#include <cuda_runtime.h>
#include <math.h>

#define NODES 100000
#define EDGES_MAX 1600000
#define FEAT  128
#define SCAN_B 256
#define NBLK_SCAN ((NODES + SCAN_B - 1) / SCAN_B)   // 391

// Scratch: __device__ globals (allocation-free rule). Device-side use only.
__device__ float g_g[NODES * FEAT];      // g = (in @ W) * dinv
__device__ float g_h[NODES * FEAT];      // layer-1 output
__device__ float g_dinv[NODES];
__device__ int   g_cnt[NODES];           // in-degree histogram (no self loop)
__device__ int   g_incl[NODES];          // block-local inclusive scan
__device__ int   g_rowstart[NODES];      // CSR row starts (exclusive scan)
__device__ int   g_cur[NODES];           // placement cursors
__device__ int   g_poff[NBLK_SCAN + 1];  // per-block scan offsets
__device__ int   g_csr[EDGES_MAX];       // src indices grouped by dst
__device__ int   g_idx64;                // 1 if edge_index is int64

// ---------------------------------------------------------------------------
// dtype detection: first 256 entries as int64 all in [0,NODES) => int64.
// ---------------------------------------------------------------------------
__global__ void k_detect(const void* __restrict__ ei) {
    __shared__ int ok;
    if (threadIdx.x == 0) ok = 1;
    __syncthreads();
    long long v = ((const long long*)ei)[threadIdx.x];
    if (v < 0 || v >= NODES) ok = 0;
    __syncthreads();
    if (threadIdx.x == 0) g_idx64 = ok;
}

__device__ __forceinline__ int load_idx(const void* ei, long long elem) {
    if (g_idx64) return (int)((const long long*)ei)[elem];
    return ((const int*)ei)[elem];
}

// ---------------------------------------------------------------------------
// CSR build
// ---------------------------------------------------------------------------
__global__ void k_zero_cnt(int n) {
    int i = blockIdx.x * blockDim.x + threadIdx.x;
    if (i < n) g_cnt[i] = 0;
}

__global__ void k_hist(const void* __restrict__ ei, int E) {
    int e = blockIdx.x * blockDim.x + threadIdx.x;
    if (e >= E) return;
    int d = load_idx(ei, (long long)E + e);
    if ((unsigned)d < NODES) atomicAdd(&g_cnt[d], 1);
}

__global__ void k_scan1(int n) {
    __shared__ int sm[SCAN_B];
    int i = blockIdx.x * SCAN_B + threadIdx.x;
    int v = (i < n) ? g_cnt[i] : 0;
    sm[threadIdx.x] = v;
    __syncthreads();
#pragma unroll
    for (int o = 1; o < SCAN_B; o <<= 1) {
        int t = (threadIdx.x >= o) ? sm[threadIdx.x - o] : 0;
        __syncthreads();
        sm[threadIdx.x] += t;
        __syncthreads();
    }
    if (i < n) g_incl[i] = sm[threadIdx.x];
    if (threadIdx.x == SCAN_B - 1) g_poff[blockIdx.x] = sm[SCAN_B - 1];
}

__global__ void k_scan2() {   // single block, 512 threads >= NBLK_SCAN
    __shared__ int sm[512];
    int i = threadIdx.x;
    int v = (i < NBLK_SCAN) ? g_poff[i] : 0;
    sm[i] = v;
    __syncthreads();
#pragma unroll
    for (int o = 1; o < 512; o <<= 1) {
        int t = (i >= o) ? sm[i - o] : 0;
        __syncthreads();
        sm[i] += t;
        __syncthreads();
    }
    if (i < NBLK_SCAN) g_poff[i] = sm[i] - v;   // exclusive
}

__global__ void k_scan3(int n) {
    int i = blockIdx.x * blockDim.x + threadIdx.x;
    if (i >= n) return;
    int c = g_cnt[i];
    int rs = g_incl[i] - c + g_poff[i >> 8];    // SCAN_B == 256
    g_rowstart[i] = rs;
    g_cur[i] = rs;
    g_dinv[i] = rsqrtf((float)c + 1.0f);
}

__global__ void k_place(const void* __restrict__ ei, int E) {
    int e = blockIdx.x * blockDim.x + threadIdx.x;
    if (e >= E) return;
    int s = load_idx(ei, e);
    int d = load_idx(ei, (long long)E + e);
    if ((unsigned)s >= NODES || (unsigned)d >= NODES) return;
    int pos = atomicAdd(&g_cur[d], 1);
    g_csr[pos] = s;
}

// ---------------------------------------------------------------------------
// GEMM: g[row][c] = (sum_k A[row][k] * W[k][c]) * dinv[row].
// BM=128, BN=128, BK=32. 256 threads, 8x8 microtile.
// use_h selects internal g_h as input (layer 2).
// ---------------------------------------------------------------------------
__global__ void k_gemm_scale(const float* __restrict__ Aext,
                             const float* __restrict__ W,
                             int n, int use_h) {
    __shared__ float  xs[128 * 33];
    __shared__ float4 ws4[32 * 32];

    const float* A = use_h ? (const float*)g_h : Aext;

    int tid = threadIdx.x;
    int tx = tid & 15;
    int ty = tid >> 4;
    int row0 = blockIdx.x * 128;

    const float4* A4 = (const float4*)A;
    const float4* W4 = (const float4*)W;

    float acc[8][8];
#pragma unroll
    for (int r = 0; r < 8; r++)
#pragma unroll
        for (int c = 0; c < 8; c++) acc[r][c] = 0.f;

    for (int kc = 0; kc < 4; kc++) {
#pragma unroll
        for (int i = 0; i < 4; i++) {
            int slot = tid + i * 256;
            int r  = slot >> 3;
            int c4 = slot & 7;
            int gr = row0 + r;
            float4 v = (gr < n) ? A4[gr * 32 + kc * 8 + c4]
                                : make_float4(0.f, 0.f, 0.f, 0.f);
            float* p = &xs[r * 33 + c4 * 4];
            p[0] = v.x; p[1] = v.y; p[2] = v.z; p[3] = v.w;
        }
#pragma unroll
        for (int i = 0; i < 4; i++) {
            int slot = tid + i * 256;
            int kr = slot >> 5;
            int c4 = slot & 31;
            ws4[slot] = W4[(kc * 32 + kr) * 32 + c4];
        }
        __syncthreads();

#pragma unroll 8
        for (int k = 0; k < 32; k++) {
            float a[8];
#pragma unroll
            for (int r = 0; r < 8; r++) a[r] = xs[(ty * 8 + r) * 33 + k];
            float4 b0 = ws4[k * 32 + tx * 2];
            float4 b1 = ws4[k * 32 + tx * 2 + 1];
#pragma unroll
            for (int r = 0; r < 8; r++) {
                acc[r][0] += a[r] * b0.x;
                acc[r][1] += a[r] * b0.y;
                acc[r][2] += a[r] * b0.z;
                acc[r][3] += a[r] * b0.w;
                acc[r][4] += a[r] * b1.x;
                acc[r][5] += a[r] * b1.y;
                acc[r][6] += a[r] * b1.z;
                acc[r][7] += a[r] * b1.w;
            }
        }
        __syncthreads();
    }

    float4* gout = (float4*)g_g;
#pragma unroll
    for (int r = 0; r < 8; r++) {
        int row = row0 + ty * 8 + r;
        if (row < n) {
            float dv = g_dinv[row];
            int base = row * 32 + tx * 2;
            gout[base]     = make_float4(acc[r][0] * dv, acc[r][1] * dv,
                                         acc[r][2] * dv, acc[r][3] * dv);
            gout[base + 1] = make_float4(acc[r][4] * dv, acc[r][5] * dv,
                                         acc[r][6] * dv, acc[r][7] * dv);
        }
    }
}

// ---------------------------------------------------------------------------
// Aggregate (warp per node, no atomics):
//   acc = g[i] + sum_{e in CSR row i} g[src_e]
//   h   = relu(dinv_i * acc + b)
// FINAL=0: store h to g_h.  FINAL=1: fuse FC + log_softmax, write out.
// ---------------------------------------------------------------------------
template <int FINAL>
__global__ void k_agg(const float* __restrict__ b,
                      const float* __restrict__ Wfc,
                      const float* __restrict__ bfc,
                      float* __restrict__ out,
                      int n) {
    int widx = (blockIdx.x * blockDim.x + threadIdx.x) >> 5;
    int q = threadIdx.x & 31;
    if (widx >= n) return;

    const float4* g4 = (const float4*)g_g;
    int base = g_rowstart[widx];
    int end  = base + g_cnt[widx];

    float4 acc = g4[widx * 32 + q];       // self-loop term
    int e = base;
    for (; e + 1 < end; e += 2) {
        int s0 = g_csr[e];
        int s1 = g_csr[e + 1];
        float4 v0 = g4[s0 * 32 + q];
        float4 v1 = g4[s1 * 32 + q];
        acc.x += v0.x; acc.y += v0.y; acc.z += v0.z; acc.w += v0.w;
        acc.x += v1.x; acc.y += v1.y; acc.z += v1.z; acc.w += v1.w;
    }
    if (e < end) {
        float4 v = g4[g_csr[e] * 32 + q];
        acc.x += v.x; acc.y += v.y; acc.z += v.z; acc.w += v.w;
    }

    float dv = g_dinv[widx];
    float4 bb = ((const float4*)b)[q];
    float4 h;
    h.x = fmaxf(dv * acc.x + bb.x, 0.f);
    h.y = fmaxf(dv * acc.y + bb.y, 0.f);
    h.z = fmaxf(dv * acc.z + bb.z, 0.f);
    h.w = fmaxf(dv * acc.w + bb.w, 0.f);

    if (!FINAL) {
        ((float4*)g_h)[widx * 32 + q] = h;
    } else {
        const float4* w4 = (const float4*)Wfc;   // [128][2] => 2 rows per float4
        float4 w0 = w4[q * 2];                   // rows 4q, 4q+1
        float4 w1 = w4[q * 2 + 1];               // rows 4q+2, 4q+3
        float l0 = h.x * w0.x + h.y * w0.z + h.z * w1.x + h.w * w1.z;
        float l1 = h.x * w0.y + h.y * w0.w + h.z * w1.y + h.w * w1.w;
#pragma unroll
        for (int o = 16; o > 0; o >>= 1) {
            l0 += __shfl_xor_sync(0xffffffffu, l0, o);
            l1 += __shfl_xor_sync(0xffffffffu, l1, o);
        }
        if (q == 0) {
            l0 += bfc[0];
            l1 += bfc[1];
            float m = fmaxf(l0, l1);
            float z = m + logf(expf(l0 - m) + expf(l1 - m));
            out[widx * 2]     = l0 - z;
            out[widx * 2 + 1] = l1 - z;
        }
    }
}

// ---------------------------------------------------------------------------
extern "C" void kernel_launch(void* const* d_in, const int* in_sizes, int n_in,
                              void* d_out, int out_size) {
    const float* x   = (const float*)d_in[0];
    const void*  ei  = d_in[1];
    const float* W1  = (const float*)d_in[2];
    const float* b1  = (const float*)d_in[3];
    const float* W2  = (const float*)d_in[4];
    const float* b2  = (const float*)d_in[5];
    const float* Wfc = (const float*)d_in[6];
    const float* bfc = (const float*)d_in[7];
    float*       out = (float*)d_out;

    int n = in_sizes[0] / FEAT;
    int E = in_sizes[1] / 2;

    int tb = 256;
    int node_blocks = (n + tb - 1) / tb;
    int edge_blocks = (E + tb - 1) / tb;
    int gemm_blocks = (n + 127) / 128;
    int warp_blocks = (int)(((long long)n * 32 + tb - 1) / tb);

    // CSR build + dinv
    k_detect<<<1, 256>>>(ei);
    k_zero_cnt<<<node_blocks, tb>>>(n);
    k_hist<<<edge_blocks, tb>>>(ei, E);
    k_scan1<<<NBLK_SCAN, SCAN_B>>>(n);
    k_scan2<<<1, 512>>>();
    k_scan3<<<node_blocks, tb>>>(n);
    k_place<<<edge_blocks, tb>>>(ei, E);

    // layer 1
    k_gemm_scale<<<gemm_blocks, tb>>>(x, W1, n, 0);
    k_agg<0><<<warp_blocks, tb>>>(b1, nullptr, nullptr, nullptr, n);

    // layer 2 (+ fused FC + log_softmax)
    k_gemm_scale<<<gemm_blocks, tb>>>(x, W2, n, 1);
    k_agg<1><<<warp_blocks, tb>>>(b2, Wfc, bfc, out, n);
}

// round 6
// speedup vs baseline: 5.0257x; 1.4367x over previous
#include <cuda_runtime.h>
#include <math.h>

#define NODES 100000
#define EDGES_MAX 1600000
#define FEAT  128
#define SCAN_B 256
#define NBLK_SCAN ((NODES + SCAN_B - 1) / SCAN_B)   // 391

// Scratch: __device__ globals (allocation-free rule). Device-side use only.
__device__ float g_g[NODES * FEAT];      // g = (in @ W) * dinv
__device__ float g_h[NODES * FEAT];      // layer-1 output
__device__ float g_dinv[NODES];
__device__ int   g_cnt[NODES];           // in-degree histogram (no self loop)
__device__ int   g_incl[NODES];          // block-local inclusive scan
__device__ int   g_rowstart[NODES];      // CSR row starts
__device__ int   g_cur[NODES];           // placement cursors
__device__ int   g_poff[NBLK_SCAN + 1];
__device__ int   g_csr[EDGES_MAX];       // src indices grouped by dst
__device__ int   g_idx64;                // 1 if edge_index is int64

// ---------------------------------------------------------------------------
// init: zero histogram; block 0 also detects edge-index dtype
// (first 256 entries as int64 all in [0,NODES) => int64 layout).
// ---------------------------------------------------------------------------
__global__ void k_init(const void* __restrict__ ei, int n) {
    int i = blockIdx.x * blockDim.x + threadIdx.x;
    if (i < n) g_cnt[i] = 0;
    if (blockIdx.x == 0) {
        __shared__ int ok;
        if (threadIdx.x == 0) ok = 1;
        __syncthreads();
        long long v = ((const long long*)ei)[threadIdx.x];
        if (v < 0 || v >= NODES) ok = 0;
        __syncthreads();
        if (threadIdx.x == 0) g_idx64 = ok;
    }
}

__device__ __forceinline__ int load_idx(const void* ei, long long elem) {
    if (g_idx64) return (int)((const long long*)ei)[elem];
    return ((const int*)ei)[elem];
}

// ---------------------------------------------------------------------------
// CSR build
// ---------------------------------------------------------------------------
__global__ void k_hist(const void* __restrict__ ei, int E) {
    int e = blockIdx.x * blockDim.x + threadIdx.x;
    if (e >= E) return;
    int d = load_idx(ei, (long long)E + e);
    if ((unsigned)d < NODES) atomicAdd(&g_cnt[d], 1);
}

__global__ void k_dinv(int n) {
    int i = blockIdx.x * blockDim.x + threadIdx.x;
    if (i < n) g_dinv[i] = rsqrtf((float)g_cnt[i] + 1.0f);
}

__global__ void k_scan1(int n) {
    __shared__ int sm[SCAN_B];
    int i = blockIdx.x * SCAN_B + threadIdx.x;
    int v = (i < n) ? g_cnt[i] : 0;
    sm[threadIdx.x] = v;
    __syncthreads();
#pragma unroll
    for (int o = 1; o < SCAN_B; o <<= 1) {
        int t = (threadIdx.x >= o) ? sm[threadIdx.x - o] : 0;
        __syncthreads();
        sm[threadIdx.x] += t;
        __syncthreads();
    }
    if (i < n) g_incl[i] = sm[threadIdx.x];
    if (threadIdx.x == SCAN_B - 1) g_poff[blockIdx.x] = sm[SCAN_B - 1];
}

__global__ void k_scan2() {   // single block, 512 >= NBLK_SCAN
    __shared__ int sm[512];
    int i = threadIdx.x;
    int v = (i < NBLK_SCAN) ? g_poff[i] : 0;
    sm[i] = v;
    __syncthreads();
#pragma unroll
    for (int o = 1; o < 512; o <<= 1) {
        int t = (i >= o) ? sm[i - o] : 0;
        __syncthreads();
        sm[i] += t;
        __syncthreads();
    }
    if (i < NBLK_SCAN) g_poff[i] = sm[i] - v;   // exclusive
}

__global__ void k_scan3(int n) {
    int i = blockIdx.x * blockDim.x + threadIdx.x;
    if (i >= n) return;
    int c = g_cnt[i];
    int rs = g_incl[i] - c + g_poff[i >> 8];
    g_rowstart[i] = rs;
    g_cur[i] = rs;
}

__global__ void k_place(const void* __restrict__ ei, int E) {
    int e = blockIdx.x * blockDim.x + threadIdx.x;
    if (e >= E) return;
    int s = load_idx(ei, e);
    int d = load_idx(ei, (long long)E + e);
    if ((unsigned)s >= NODES || (unsigned)d >= NODES) return;
    int pos = atomicAdd(&g_cur[d], 1);
    g_csr[pos] = s;
}

// ---------------------------------------------------------------------------
// tf32 tensor-core GEMM: g[row][c] = (sum_k A[row][k] * W[k][c]) * dinv[row]
// BM=128, BN=128, BK=32 (4 chunks). 256 thr = 8 warps, warp tile 32x64.
// mma.sync m16n8k8 tf32. tf32 conversion at smem staging.
// use_h selects internal g_h as input (layer 2).
// ---------------------------------------------------------------------------
#define PAD_A 36
#define PAD_W 132

__device__ __forceinline__ float to_tf32(float x) {
    unsigned u;
    asm("cvt.rna.tf32.f32 %0, %1;" : "=r"(u) : "f"(x));
    return __uint_as_float(u);
}

__global__ void __launch_bounds__(256)
k_gemm_tf32(const float* __restrict__ Aext, const float* __restrict__ W,
            int n, int use_h) {
    __shared__ float As[128 * PAD_A];   // 18432 B
    __shared__ float Ws[32 * PAD_W];    // 16896 B

    const float* A = use_h ? (const float*)g_h : Aext;

    int tid  = threadIdx.x;
    int wid  = tid >> 5;
    int lane = tid & 31;
    int gq   = lane >> 2;   // groupID 0..7
    int tq   = lane & 3;    // thread-in-group 0..3
    int warp_m = wid & 3;   // rows 32*warp_m .. +31
    int warp_n = wid >> 2;  // cols 64*warp_n .. +63
    int row0 = blockIdx.x * 128;

    const float4* A4 = (const float4*)A;
    const float4* W4 = (const float4*)W;

    float acc[2][8][4];
#pragma unroll
    for (int mt = 0; mt < 2; mt++)
#pragma unroll
        for (int nt = 0; nt < 8; nt++)
#pragma unroll
            for (int r = 0; r < 4; r++) acc[mt][nt][r] = 0.f;

    for (int kc = 0; kc < 4; kc++) {
        // stage A chunk [128 rows][32 k], tf32-rounded
#pragma unroll
        for (int i = 0; i < 4; i++) {
            int slot = tid + i * 256;          // 0..1023
            int r  = slot >> 3;
            int c4 = slot & 7;
            int gr = row0 + r;
            float4 v = (gr < n) ? A4[gr * 32 + kc * 8 + c4]
                                : make_float4(0.f, 0.f, 0.f, 0.f);
            float* p = &As[r * PAD_A + c4 * 4];
            p[0] = to_tf32(v.x); p[1] = to_tf32(v.y);
            p[2] = to_tf32(v.z); p[3] = to_tf32(v.w);
        }
        // stage W chunk [32 k][128 cols], tf32-rounded
#pragma unroll
        for (int i = 0; i < 4; i++) {
            int slot = tid + i * 256;
            int kr = slot >> 5;
            int c4 = slot & 31;
            float4 v = W4[(kc * 32 + kr) * 32 + c4];
            float* p = &Ws[kr * PAD_W + c4 * 4];
            p[0] = to_tf32(v.x); p[1] = to_tf32(v.y);
            p[2] = to_tf32(v.z); p[3] = to_tf32(v.w);
        }
        __syncthreads();

#pragma unroll
        for (int ks = 0; ks < 4; ks++) {
            int k0 = ks * 8;
            float a[2][4];
#pragma unroll
            for (int mt = 0; mt < 2; mt++) {
                int r0 = warp_m * 32 + mt * 16;
                a[mt][0] = As[(r0 + gq)     * PAD_A + k0 + tq];
                a[mt][1] = As[(r0 + gq + 8) * PAD_A + k0 + tq];
                a[mt][2] = As[(r0 + gq)     * PAD_A + k0 + tq + 4];
                a[mt][3] = As[(r0 + gq + 8) * PAD_A + k0 + tq + 4];
            }
#pragma unroll
            for (int nt = 0; nt < 8; nt++) {
                int c0 = warp_n * 64 + nt * 8;
                unsigned b0 = __float_as_uint(Ws[(k0 + tq)     * PAD_W + c0 + gq]);
                unsigned b1 = __float_as_uint(Ws[(k0 + tq + 4) * PAD_W + c0 + gq]);
#pragma unroll
                for (int mt = 0; mt < 2; mt++) {
                    asm volatile(
                        "mma.sync.aligned.m16n8k8.row.col.f32.tf32.tf32.f32 "
                        "{%0,%1,%2,%3}, {%4,%5,%6,%7}, {%8,%9}, {%0,%1,%2,%3};"
                        : "+f"(acc[mt][nt][0]), "+f"(acc[mt][nt][1]),
                          "+f"(acc[mt][nt][2]), "+f"(acc[mt][nt][3])
                        : "r"(__float_as_uint(a[mt][0])),
                          "r"(__float_as_uint(a[mt][1])),
                          "r"(__float_as_uint(a[mt][2])),
                          "r"(__float_as_uint(a[mt][3])),
                          "r"(b0), "r"(b1));
                }
            }
        }
        __syncthreads();
    }

    // epilogue: scale by dinv[row], write g_g
#pragma unroll
    for (int mt = 0; mt < 2; mt++) {
        int rlo = row0 + warp_m * 32 + mt * 16 + gq;
        int rhi = rlo + 8;
        float dlo = (rlo < n) ? g_dinv[rlo] : 0.f;
        float dhi = (rhi < n) ? g_dinv[rhi] : 0.f;
#pragma unroll
        for (int nt = 0; nt < 8; nt++) {
            int c = warp_n * 64 + nt * 8 + 2 * tq;
            if (rlo < n) {
                float2 v = make_float2(acc[mt][nt][0] * dlo, acc[mt][nt][1] * dlo);
                *(float2*)&g_g[rlo * 128 + c] = v;
            }
            if (rhi < n) {
                float2 v = make_float2(acc[mt][nt][2] * dhi, acc[mt][nt][3] * dhi);
                *(float2*)&g_g[rhi * 128 + c] = v;
            }
        }
    }
}

// ---------------------------------------------------------------------------
// Aggregate (warp per node, no atomics, unroll x4 for MLP):
//   acc = g[i] + sum_{e in CSR row i} g[src_e];  h = relu(dinv_i*acc + b)
// FINAL=1 fuses FC + log_softmax.
// ---------------------------------------------------------------------------
template <int FINAL>
__global__ void k_agg(const float* __restrict__ b,
                      const float* __restrict__ Wfc,
                      const float* __restrict__ bfc,
                      float* __restrict__ out,
                      int n) {
    int widx = (blockIdx.x * blockDim.x + threadIdx.x) >> 5;
    int q = threadIdx.x & 31;
    if (widx >= n) return;

    const float4* g4 = (const float4*)g_g;
    int base = g_rowstart[widx];
    int end  = base + g_cnt[widx];

    float4 acc = g4[widx * 32 + q];       // self-loop term
    int e = base;
    for (; e + 4 <= end; e += 4) {
        int s0 = g_csr[e];
        int s1 = g_csr[e + 1];
        int s2 = g_csr[e + 2];
        int s3 = g_csr[e + 3];
        float4 v0 = g4[s0 * 32 + q];
        float4 v1 = g4[s1 * 32 + q];
        float4 v2 = g4[s2 * 32 + q];
        float4 v3 = g4[s3 * 32 + q];
        acc.x += v0.x + v1.x + v2.x + v3.x;
        acc.y += v0.y + v1.y + v2.y + v3.y;
        acc.z += v0.z + v1.z + v2.z + v3.z;
        acc.w += v0.w + v1.w + v2.w + v3.w;
    }
    for (; e < end; e++) {
        float4 v = g4[g_csr[e] * 32 + q];
        acc.x += v.x; acc.y += v.y; acc.z += v.z; acc.w += v.w;
    }

    float dv = g_dinv[widx];
    float4 bb = ((const float4*)b)[q];
    float4 h;
    h.x = fmaxf(dv * acc.x + bb.x, 0.f);
    h.y = fmaxf(dv * acc.y + bb.y, 0.f);
    h.z = fmaxf(dv * acc.z + bb.z, 0.f);
    h.w = fmaxf(dv * acc.w + bb.w, 0.f);

    if (!FINAL) {
        ((float4*)g_h)[widx * 32 + q] = h;
    } else {
        const float4* w4 = (const float4*)Wfc;   // [128][2]: 2 rows per float4
        float4 w0 = w4[q * 2];
        float4 w1 = w4[q * 2 + 1];
        float l0 = h.x * w0.x + h.y * w0.z + h.z * w1.x + h.w * w1.z;
        float l1 = h.x * w0.y + h.y * w0.w + h.z * w1.y + h.w * w1.w;
#pragma unroll
        for (int o = 16; o > 0; o >>= 1) {
            l0 += __shfl_xor_sync(0xffffffffu, l0, o);
            l1 += __shfl_xor_sync(0xffffffffu, l1, o);
        }
        if (q == 0) {
            l0 += bfc[0];
            l1 += bfc[1];
            float m = fmaxf(l0, l1);
            float z = m + logf(expf(l0 - m) + expf(l1 - m));
            out[widx * 2]     = l0 - z;
            out[widx * 2 + 1] = l1 - z;
        }
    }
}

// ---------------------------------------------------------------------------
extern "C" void kernel_launch(void* const* d_in, const int* in_sizes, int n_in,
                              void* d_out, int out_size) {
    const float* x   = (const float*)d_in[0];
    const void*  ei  = d_in[1];
    const float* W1  = (const float*)d_in[2];
    const float* b1  = (const float*)d_in[3];
    const float* W2  = (const float*)d_in[4];
    const float* b2  = (const float*)d_in[5];
    const float* Wfc = (const float*)d_in[6];
    const float* bfc = (const float*)d_in[7];
    float*       out = (float*)d_out;

    int n = in_sizes[0] / FEAT;
    int E = in_sizes[1] / 2;

    int tb = 256;
    int node_blocks = (n + tb - 1) / tb;
    int edge_blocks = (E + tb - 1) / tb;
    int gemm_blocks = (n + 127) / 128;
    int warp_blocks = (int)(((long long)n * 32 + tb - 1) / tb);

    // 1-3: histogram + dinv (gemm needs only dinv)
    k_init<<<node_blocks, tb>>>(ei, n);
    k_hist<<<edge_blocks, tb>>>(ei, E);
    k_dinv<<<node_blocks, tb>>>(n);

    // 4: layer-1 GEMM (profiled launch)
    k_gemm_tf32<<<gemm_blocks, tb>>>(x, W1, n, 0);

    // 5-8: CSR finalize
    k_scan1<<<NBLK_SCAN, SCAN_B>>>(n);
    k_scan2<<<1, 512>>>();
    k_scan3<<<node_blocks, tb>>>(n);
    k_place<<<edge_blocks, tb>>>(ei, E);

    // 9: layer-1 aggregate
    k_agg<0><<<warp_blocks, tb>>>(b1, nullptr, nullptr, nullptr, n);

    // 10-11: layer 2 + fused FC/log_softmax
    k_gemm_tf32<<<gemm_blocks, tb>>>(x, W2, n, 1);
    k_agg<1><<<warp_blocks, tb>>>(b2, Wfc, bfc, out, n);
}